// round 9
// baseline (speedup 1.0000x reference)
#include <cuda_runtime.h>
#include <cstdint>
#include <cstddef>

// out[t,e,o] = sum_r x[t, e*128+r] * W[e,o,r]
// x: [8192, 1024] f32, W: [8, 4096, 128] f32, out: [8192, 8, 4096] f32
//
// mma.sync TF32 (tcgen05 unavailable: harness compiles via compute_103 PTX).
// Round 9: persistent CTAs. Grid = 16 N-tiles x 8 experts = 128 CTAs (1 wave).
// W tile [256x128] (pre-rounded tf32) resident in SMEM, loaded once by cp.async.
// X streamed per 64-row M-iter through a 2x32KB cp.async double buffer issued
// by the compute warps themselves (no producer warps / mbarriers).
// Warp tile 32x64, LDS.64 k-slot-permutation fragments (R7 scheme).

#define EXPERTS 8
#define RANK    128
#define OUTF    4096
#define TOKENS  8192
#define BMI     64          // M rows per iteration
#define BN      256

#define SM_X    0                         // 2 x 32768
#define SM_W    65536                     // 256 x 128 tf32 swizzled = 128KB
#define SMEM_TOTAL (65536 + 131072)       // 192KB

__device__ float g_Xr[(size_t)TOKENS * EXPERTS * RANK];   // 32MB tf32-rounded x
__device__ float g_Wr[(size_t)EXPERTS * OUTF * RANK];     // 16MB tf32-rounded W

__device__ __forceinline__ uint32_t tf32u(float f) {
    uint32_t u;
    asm("cvt.rna.tf32.f32 %0, %1;" : "=r"(u) : "f"(f));
    return u;
}
__device__ __forceinline__ uint32_t smem_u32(const void* p) {
    uint32_t a;
    asm("{ .reg .u64 t; cvta.to.shared.u64 t, %1; cvt.u32.u64 %0, t; }" : "=r"(a) : "l"(p));
    return a;
}
__device__ __forceinline__ void cp16(uint32_t dst, const void* src) {
    asm volatile("cp.async.cg.shared.global [%0], [%1], 16;" :: "r"(dst), "l"(src) : "memory");
}
__device__ __forceinline__ void mma_tf32(float c[4],
                                         uint32_t a0, uint32_t a1, uint32_t a2, uint32_t a3,
                                         uint32_t b0, uint32_t b1) {
    asm volatile(
        "mma.sync.aligned.m16n8k8.row.col.f32.tf32.tf32.f32 "
        "{%0,%1,%2,%3}, {%4,%5,%6,%7}, {%8,%9}, {%0,%1,%2,%3};"
        : "+f"(c[0]), "+f"(c[1]), "+f"(c[2]), "+f"(c[3])
        : "r"(a0), "r"(a1), "r"(a2), "r"(a3), "r"(b0), "r"(b1));
}

// ---- streaming pre-round kernels ----
__global__ void __launch_bounds__(1024, 2) round_x(const float4* __restrict__ src, int n4) {
    int i = blockIdx.x * blockDim.x + threadIdx.x;
    if (i < n4) {
        float4 v = src[i];
        reinterpret_cast<uint4*>(g_Xr)[i] =
            make_uint4(tf32u(v.x), tf32u(v.y), tf32u(v.z), tf32u(v.w));
    }
}
__global__ void __launch_bounds__(1024, 2) round_w(const float4* __restrict__ src, int n4) {
    int i = blockIdx.x * blockDim.x + threadIdx.x;
    if (i < n4) {
        float4 v = src[i];
        reinterpret_cast<uint4*>(g_Wr)[i] =
            make_uint4(tf32u(v.x), tf32u(v.y), tf32u(v.z), tf32u(v.w));
    }
}

// issue cp.async for X iteration 'it' into buffer 'buf' (8 x 16B per thread)
__device__ __forceinline__ void issue_x(uint32_t sb, int buf, int it, int e, int tid) {
    const float* src = g_Xr + (size_t)(it * BMI) * (EXPERTS * RANK) + e * RANK;
    const uint32_t dbase = sb + SM_X + (uint32_t)buf * 32768;
    #pragma unroll
    for (int p = 0; p < 8; ++p) {
        int idx = p * 256 + tid;
        int row = idx >> 5;                  // 0..63
        int q   = idx & 31;                  // float4 slot
        uint32_t dst = dbase + (uint32_t)row * 512
                     + (((uint32_t)q * 16) ^ (((uint32_t)row & 7) << 5));
        cp16(dst, src + (size_t)row * (EXPERTS * RANK) + q * 4);
    }
}

extern "C" __global__ void __launch_bounds__(256, 1)
moelb_v6(float* __restrict__ out, int iters)
{
    extern __shared__ char smem[];
    const uint32_t sb = smem_u32(smem);
    float* Ws = reinterpret_cast<float*>(smem + SM_W);

    const int tid  = threadIdx.x;
    const int wid  = tid >> 5;
    const int lane = tid & 31;
    const int g    = lane >> 2;
    const int tig  = lane & 3;

    const int nOff = blockIdx.x * BN;
    const int e    = blockIdx.y;

    // ---- prologue: W tile (resident) + first X iter -> group 0; X iter 1 -> group 1 ----
    {
        const float* wsrc = g_Wr + ((size_t)e * OUTF + nOff) * RANK;
        #pragma unroll
        for (int p = 0; p < 32; ++p) {
            int idx = p * 256 + tid;
            int row = idx >> 5;              // 0..255
            int q   = idx & 31;
            uint32_t dst = sb + SM_W + (uint32_t)row * 512
                         + (((uint32_t)q * 16) ^ (((uint32_t)row & 7) << 5));
            cp16(dst, wsrc + (size_t)row * RANK + q * 4);
        }
        issue_x(sb, 0, 0, e, tid);
        asm volatile("cp.async.commit_group;" ::: "memory");
        issue_x(sb, 1, 1, e, tid);
        asm volatile("cp.async.commit_group;" ::: "memory");
    }

    // ---- warp mapping: warp tile 32(M) x 64(N) ----
    const int mW  = (wid >> 2) * 32;        // 0 or 32
    const int nW  = (wid & 3) * 64;         // 0,64,128,192
    const int skf = g << 3;
    const int t2  = tig << 1;

    int aRow[2][2], bRow[8];
    #pragma unroll
    for (int mt = 0; mt < 2; ++mt) {
        aRow[mt][0] = (mW + mt * 16 + g) * RANK;
        aRow[mt][1] = (mW + mt * 16 + 8 + g) * RANK;
    }
    #pragma unroll
    for (int nt = 0; nt < 8; ++nt)
        bRow[nt] = (nW + nt * 8 + g) * RANK;

    for (int it = 0; it < iters; ++it) {
        const int buf = it & 1;
        const float* Xs = reinterpret_cast<float*>(smem + SM_X + buf * 32768);

        asm volatile("cp.async.wait_group 1;" ::: "memory");
        __syncthreads();

        float acc[2][8][4];
        #pragma unroll
        for (int mt = 0; mt < 2; ++mt)
            #pragma unroll
            for (int nt = 0; nt < 8; ++nt)
                #pragma unroll
                for (int i = 0; i < 4; ++i)
                    acc[mt][nt][i] = 0.0f;

        float2 Af[2][2][2];
        float2 Bf[2][8];
        {
            const int o = (0 ^ skf) + t2;
            #pragma unroll
            for (int mt = 0; mt < 2; ++mt) {
                Af[0][mt][0] = *reinterpret_cast<const float2*>(&Xs[aRow[mt][0] + o]);
                Af[0][mt][1] = *reinterpret_cast<const float2*>(&Xs[aRow[mt][1] + o]);
            }
            #pragma unroll
            for (int nt = 0; nt < 8; ++nt)
                Bf[0][nt] = *reinterpret_cast<const float2*>(&Ws[bRow[nt] + o]);
        }

        #pragma unroll
        for (int j = 0; j < 16; ++j) {
            const int s = j & 1;
            if (j < 15) {
                const int o = (((j + 1) << 3) ^ skf) + t2;
                const int n = s ^ 1;
                #pragma unroll
                for (int mt = 0; mt < 2; ++mt) {
                    Af[n][mt][0] = *reinterpret_cast<const float2*>(&Xs[aRow[mt][0] + o]);
                    Af[n][mt][1] = *reinterpret_cast<const float2*>(&Xs[aRow[mt][1] + o]);
                }
                #pragma unroll
                for (int nt = 0; nt < 8; ++nt)
                    Bf[n][nt] = *reinterpret_cast<const float2*>(&Ws[bRow[nt] + o]);
            }
            #pragma unroll
            for (int mt = 0; mt < 2; ++mt) {
                uint32_t a0 = __float_as_uint(Af[s][mt][0].x);
                uint32_t a1 = __float_as_uint(Af[s][mt][1].x);
                uint32_t a2 = __float_as_uint(Af[s][mt][0].y);
                uint32_t a3 = __float_as_uint(Af[s][mt][1].y);
                #pragma unroll
                for (int nt = 0; nt < 8; ++nt)
                    mma_tf32(acc[mt][nt], a0, a1, a2, a3,
                             __float_as_uint(Bf[s][nt].x), __float_as_uint(Bf[s][nt].y));
            }
        }

        __syncthreads();                      // all warps done reading buf

        if (it + 2 < iters) issue_x(sb, buf, it + 2, e, tid);
        asm volatile("cp.async.commit_group;" ::: "memory");

        // ---- epilogue (overlaps with in-flight cp.async) ----
        #pragma unroll
        for (int mt = 0; mt < 2; ++mt) {
            const int t0 = it * BMI + mW + mt * 16 + g;
            float* p0 = out + ((size_t)t0 * EXPERTS + e) * OUTF + nOff + nW;
            float* p1 = p0 + (size_t)8 * EXPERTS * OUTF;
            #pragma unroll
            for (int nt = 0; nt < 8; ++nt) {
                int o = nt * 8 + 2 * tig;
                *reinterpret_cast<float2*>(p0 + o) = make_float2(acc[mt][nt][0], acc[mt][nt][1]);
                *reinterpret_cast<float2*>(p1 + o) = make_float2(acc[mt][nt][2], acc[mt][nt][3]);
            }
        }
    }
}

extern "C" void kernel_launch(void* const* d_in, const int* in_sizes, int n_in,
                              void* d_out, int out_size)
{
    const float* x = (const float*)d_in[0];
    const float* W = (const float*)d_in[1];
    float* out = (float*)d_out;

    const int T = in_sizes[0] / (EXPERTS * RANK);

    const int nx4 = in_sizes[0] / 4;
    const int nw4 = in_sizes[1] / 4;
    round_x<<<(nx4 + 1023) / 1024, 1024>>>((const float4*)x, nx4);
    round_w<<<(nw4 + 1023) / 1024, 1024>>>((const float4*)W, nw4);

    cudaFuncSetAttribute(moelb_v6,
                         cudaFuncAttributeMaxDynamicSharedMemorySize, SMEM_TOTAL);

    dim3 grid(OUTF / BN, EXPERTS);
    moelb_v6<<<grid, 256, SMEM_TOTAL>>>(out, T / BMI);
}